// round 7
// baseline (speedup 1.0000x reference)
#include <cuda_runtime.h>
#include <cuda_bf16.h>
#include <cooperative_groups.h>

namespace cg = cooperative_groups;

#define N_ST   512
#define N_OBSV 1024
#define BATCH  64
#define TMAXL  512
#define CLUSTER_N 4
#define THREADS 512

/* ---- device scratch (no allocs) ----
   g_Pp: packed-pair P, laid out per (rank, ks, lane) thread:
   idx = ((rank*16 + ks)*32 + lane)*64 + r*16 + kp
   value = pack(P[row][2k], P[row][2k+1]) with row = rank*128 + lane*4 + r,
   k-pair kp within slice ks (k = ks*32 + 2*kp {+1}).                     */
__device__ unsigned g_Pp[512 * 256];
__device__ float g_logET[N_OBSV * N_ST]; /* [obs][state] log emission  */
__device__ float g_expET[N_OBSV * N_ST]; /* [obs][state] emission prob */
__device__ float g_logPi[N_ST];
__device__ float g_icolsum[N_ST];

/* ---------------- PTX helpers ---------------- */

__device__ __forceinline__ unsigned s2u(const void* p) {
    return (unsigned)__cvta_generic_to_shared(p);
}

#define FMA2(acc, a, w) \
    asm("fma.rn.f32x2 %0, %1, %2, %0;" : "+l"(acc) : "l"(a), "l"(w))

#define MBARRIER_INIT(mbar, count) \
    asm volatile("mbarrier.init.shared.b64 [%0], %1;" \
        :: "r"(mbar), "r"((unsigned)(count)) : "memory")

#define MBARRIER_ARRIVE_CLUSTER(local_mbar, target_rank) \
    asm volatile( \
        "{\n\t" \
        ".reg .b32 remAddr32;\n\t" \
        "mapa.shared::cluster.u32 remAddr32, %0, %1;\n\t" \
        "mbarrier.arrive.release.cluster.shared::cluster.b64 _, [remAddr32];\n\t" \
        "}" \
        :: "r"(local_mbar), "r"((unsigned)(target_rank)) : "memory")

#define MBARRIER_WAIT_PARITY(mbar, parity) do { \
    unsigned _m = (mbar), _p = (parity), _done; \
    asm volatile( \
        "{\n\t.reg .pred p;\n\t" \
        "mbarrier.try_wait.parity.acquire.cta.shared::cta.b64 p, [%1], %2;\n\t" \
        "selp.b32 %0, 1, 0, p;\n\t}" \
        : "=r"(_done) : "r"(_m), "r"(_p) : "memory"); \
    if (!_done) { \
        asm volatile( \
            "{\n\t.reg .pred P1;\n\t" \
            "WL_%=:\n\t" \
            "mbarrier.try_wait.parity.acquire.cta.shared::cta.b64 P1, [%0], %1, 0x989680;\n\t" \
            "@P1 bra.uni WD_%=;\n\t" \
            "bra.uni WL_%=;\n\t" \
            "WD_%=:\n\t}" \
            :: "r"(_m), "r"(_p) : "memory"); \
    } \
} while (0)

/* ---------------- prep kernels ---------------- */

__global__ void prep_logpi(const float* __restrict__ pi) {
    __shared__ float red[8];
    int tid = threadIdx.x;
    float s = 0.f;
    for (int k = tid; k < N_ST; k += 256) s += __expf(pi[k]);
    for (int o = 16; o; o >>= 1) s += __shfl_xor_sync(0xffffffffu, s, o);
    if ((tid & 31) == 0) red[tid >> 5] = s;
    __syncthreads();
    float tot = 0.f;
    #pragma unroll
    for (int w = 0; w < 8; w++) tot += red[w];
    float l = __logf(tot);
    for (int k = tid; k < N_ST; k += 256) g_logPi[k] = pi[k] - l;
}

__global__ void prep_colsum(const float* __restrict__ A) {
    __shared__ float part[8][32];
    int kx = threadIdx.x & 31, iy = threadIdx.x >> 5;
    int k = blockIdx.x * 32 + kx;
    float s = 0.f;
    for (int i = iy; i < N_ST; i += 8) s += __expf(A[i * N_ST + k]);
    part[iy][kx] = s;
    __syncthreads();
    if (iy == 0) {
        float t = 0.f;
        #pragma unroll
        for (int j = 0; j < 8; j++) t += part[j][kx];
        g_icolsum[k] = 1.0f / t;
    }
}

/* low16 = bf16(pe) (recovered exactly via <<16); high16 rounded at prep so the
   raw u32 reinterpreted as f32 is the nearest repr of po given fixed low bits */
__device__ __forceinline__ unsigned pack_pair(float pe, float po) {
    unsigned lo = (unsigned)__bfloat16_as_ushort(__float2bfloat16(pe));
    unsigned ob = __float_as_uint(po);
    unsigned hi = (ob - lo + 0x8000u) >> 16;
    return lo | (hi << 16);
}

__global__ void prep_pt(const float* __restrict__ A) {
    int i   = blockIdx.x;        /* global row  */
    int kpg = threadIdx.x;       /* global k-pair 0..255 */
    float p0 = __expf(A[i * N_ST + 2 * kpg])     * g_icolsum[2 * kpg];
    float p1 = __expf(A[i * N_ST + 2 * kpg + 1]) * g_icolsum[2 * kpg + 1];
    int rank = i >> 7, lane = (i & 127) >> 2, r = i & 3;
    int ks = kpg >> 4, kp = kpg & 15;
    g_Pp[(((rank * 16 + ks) * 32) + lane) * 64 + r * 16 + kp] = pack_pair(p0, p1);
}

__global__ void prep_logE(const float* __restrict__ E) {
    __shared__ float red[8];
    int i = blockIdx.x;
    int tid = threadIdx.x;
    float s = 0.f;
    for (int o = tid; o < N_OBSV; o += 256) s += __expf(E[i * N_OBSV + o]);
    for (int o = 16; o; o >>= 1) s += __shfl_xor_sync(0xffffffffu, s, o);
    if ((tid & 31) == 0) red[tid >> 5] = s;
    __syncthreads();
    float tot = 0.f;
    #pragma unroll
    for (int w = 0; w < 8; w++) tot += red[w];
    float l = __logf(tot);
    for (int o = tid; o < N_OBSV; o += 256) {
        float lv = E[i * N_OBSV + o] - l;
        g_logET[o * N_ST + i] = lv;
        g_expET[o * N_ST + i] = __expf(lv);
    }
}

/* ---------------- main persistent clustered kernel ---------------- */

#define U_STRIDE 544                               /* 512 u + 16 partials + pad */
#define U_OFF    0
#define PD_OFF   (U_OFF + 2 * 2 * U_STRIDE * 4)    /* 8704  */
#define XS_OFF   (PD_OFF + 16 * 2 * 128 * 4)       /* 25088 */
#define BAR_OFF  (XS_OFF + 2 * TMAXL * 4)          /* 29184 */
#define RED_OFF  (BAR_OFF + 16)
#define SMEM_TOTAL (RED_OFF + 64)

extern __shared__ unsigned char smem_raw[];

__global__ void __cluster_dims__(CLUSTER_N, 1, 1) __launch_bounds__(THREADS, 1)
hmm_main(const int* __restrict__ x, const int* __restrict__ Tarr,
         float* __restrict__ out)
{
    cg::cluster_group cluster = cg::this_cluster();
    const unsigned rank = cluster.block_rank();
    const unsigned grp  = blockIdx.x / CLUSTER_N;

    float* uarr = (float*)(smem_raw + U_OFF);      /* [(buf*2+b)*U_STRIDE+.] */
    float* pdot = (float*)(smem_raw + PD_OFF);     /* [(ks*2+b)*128 + il]    */
    int*   xs   = (int*)(smem_raw + XS_OFF);       /* [b][512]               */
    float* red  = (float*)(smem_raw + RED_OFF);
    const unsigned bar0 = s2u(smem_raw + BAR_OFF);
    const unsigned bar1 = bar0 + 8;

    const int tid  = threadIdx.x;
    const int lane = tid & 31;
    const int warp = tid >> 5;       /* = ks in dot phase */
    const int b2   = (tid >> 7) & 1; /* batch id in scalar phases (tid<256) */
    const int il   = tid & 127;
    const int iglob = rank * 128 + il;

    if (tid == 0) { MBARRIER_INIT(bar0, CLUSTER_N); MBARRIER_INIT(bar1, CLUSTER_N); }

    /* ---- load this thread's 64 packed P values into registers ---- */
    unsigned Preg[64];
    {
        const uint4* Pg = (const uint4*)&g_Pp[((rank * 16 + warp) * 32 + lane) * 64];
        #pragma unroll
        for (int q = 0; q < 16; ++q) {
            uint4 v = Pg[q];
            Preg[q * 4 + 0] = v.x; Preg[q * 4 + 1] = v.y;
            Preg[q * 4 + 2] = v.z; Preg[q * 4 + 3] = v.w;
        }
    }

    /* preload observation sequences into smem */
    for (int s = tid; s < 2 * TMAXL; s += THREADS)
        xs[s] = x[grp * 2 * TMAXL + s];

    const int T0v = Tarr[grp * 2 + 0];
    const int T1v = Tarr[grp * 2 + 1];
    const int Tc  = max(T0v, T1v);

    /* ---- init: u_0 = exp(alpha0 - m), full & replicated per CTA ---- */
    float C0 = 0.f, C1 = 0.f;
    float a0i[4];
    if (tid < 256) {
        __syncthreads();   /* xs visible */
        int x0 = xs[b2 * TMAXL];
        float lm = -3.402823466e38f;
        #pragma unroll
        for (int j = 0; j < 4; j++) {
            int s = il + 128 * j;
            a0i[j] = g_logPi[s] + g_logET[x0 * N_ST + s];
            lm = fmaxf(lm, a0i[j]);
        }
        #pragma unroll
        for (int o = 16; o; o >>= 1) lm = fmaxf(lm, __shfl_xor_sync(0xffffffffu, lm, o));
        if (lane == 0) red[warp] = lm;
    } else {
        __syncthreads();
    }
    __syncthreads();
    {
        const float m0 = fmaxf(fmaxf(red[0], red[1]), fmaxf(red[2], red[3]));
        const float m1 = fmaxf(fmaxf(red[4], red[5]), fmaxf(red[6], red[7]));
        C0 = m0; C1 = m1;
        if (tid < 256) {
            const float m = b2 ? m1 : m0;
            float* u0b = uarr + b2 * U_STRIDE;
            float ls = 0.f;
            #pragma unroll
            for (int j = 0; j < 4; j++) {
                int s = il + 128 * j;
                float uv = __expf(a0i[j] - m);
                u0b[s] = uv;
                ls += uv;
            }
            #pragma unroll
            for (int o = 16; o; o >>= 1) ls += __shfl_xor_sync(0xffffffffu, ls, o);
            if (lane == 0) u0b[512 + (warp & 3)] = ls;
            if (il >= 4 && il < 16) u0b[512 + il] = 0.f;
        }
        __syncthreads();
    }
    cluster.sync();   /* barrier init + u0 ready everywhere */

    unsigned ph0 = 0, ph1 = 0;

    for (int t = 0; t < Tc; ++t) {
        if (t > 0) {
            if ((t - 1) & 1) { MBARRIER_WAIT_PARITY(bar1, ph1); ph1 ^= 1; }
            else             { MBARRIER_WAIT_PARITY(bar0, ph0); ph0 ^= 1; }
        }

        const int buf = t & 1;
        float* ub0 = uarr + (buf * 2 + 0) * U_STRIDE;
        float* ub1 = uarr + (buf * 2 + 1) * U_STRIDE;

        /* S = sum of 16 partials per batch (uniform broadcast loads) */
        float4 p0a = *(const float4*)(ub0 + 512), p0b = *(const float4*)(ub0 + 516);
        float4 p0c = *(const float4*)(ub0 + 520), p0d = *(const float4*)(ub0 + 524);
        float4 p1a = *(const float4*)(ub1 + 512), p1b = *(const float4*)(ub1 + 516);
        float4 p1c = *(const float4*)(ub1 + 520), p1d = *(const float4*)(ub1 + 524);
        const float S0 = (((p0a.x + p0a.y) + (p0a.z + p0a.w)) + ((p0b.x + p0b.y) + (p0b.z + p0b.w)))
                       + (((p0c.x + p0c.y) + (p0c.z + p0c.w)) + ((p0d.x + p0d.y) + (p0d.z + p0d.w)));
        const float S1 = (((p1a.x + p1a.y) + (p1a.z + p1a.w)) + ((p1b.x + p1b.y) + (p1b.z + p1b.w)))
                       + (((p1c.x + p1c.y) + (p1c.z + p1c.w)) + ((p1d.x + p1d.y) + (p1d.z + p1d.w)));
        C0 += __logf(S0);
        C1 += __logf(S1);

        if (rank == 0 && tid == 0) {
            if (t == T0v - 1) out[grp * 2 + 0] = C0;
            if (t == T1v - 1) out[grp * 2 + 1] = C1;
        }
        if (t == Tc - 1) break;

        /* prefetch emission for phase 2 (only warps 0-7 need it) */
        float em = 0.f, invS = 0.f;
        if (tid < 256) {
            const int xv = xs[b2 * TMAXL + t + 1];
            em   = g_expET[xv * N_ST + iglob];
            invS = __frcp_rn(b2 ? S1 : S0);
        }

        /* ---- dot phase: warp = k-slice (32 k), lane = 4-row group ----
           P from registers, w broadcast from smem, FFMA2 accumulate      */
        {
            const ulonglong2* U0 = (const ulonglong2*)(ub0 + warp * 32);
            const ulonglong2* U1 = (const ulonglong2*)(ub1 + warp * 32);
            unsigned long long accA[4] = {0ull, 0ull, 0ull, 0ull};
            unsigned long long accB[4] = {0ull, 0ull, 0ull, 0ull};

            #pragma unroll
            for (int kp2 = 0; kp2 < 8; ++kp2) {
                ulonglong2 W0 = U0[kp2];
                ulonglong2 W1 = U1[kp2];
                #pragma unroll
                for (int r = 0; r < 4; ++r) {
                    unsigned q0 = Preg[r * 16 + 2 * kp2];
                    unsigned q1 = Preg[r * 16 + 2 * kp2 + 1];
                    unsigned long long a0 =
                        ((unsigned long long)q0 << 32) | (unsigned)(q0 << 16);
                    unsigned long long a1 =
                        ((unsigned long long)q1 << 32) | (unsigned)(q1 << 16);
                    FMA2(accA[r], a0, W0.x);
                    FMA2(accA[r], a1, W0.y);
                    FMA2(accB[r], a0, W1.x);
                    FMA2(accB[r], a1, W1.y);
                }
            }

            float4 ra, rb;
            ra.x = __uint_as_float((unsigned)accA[0]) + __uint_as_float((unsigned)(accA[0] >> 32));
            ra.y = __uint_as_float((unsigned)accA[1]) + __uint_as_float((unsigned)(accA[1] >> 32));
            ra.z = __uint_as_float((unsigned)accA[2]) + __uint_as_float((unsigned)(accA[2] >> 32));
            ra.w = __uint_as_float((unsigned)accA[3]) + __uint_as_float((unsigned)(accA[3] >> 32));
            rb.x = __uint_as_float((unsigned)accB[0]) + __uint_as_float((unsigned)(accB[0] >> 32));
            rb.y = __uint_as_float((unsigned)accB[1]) + __uint_as_float((unsigned)(accB[1] >> 32));
            rb.z = __uint_as_float((unsigned)accB[2]) + __uint_as_float((unsigned)(accB[2] >> 32));
            rb.w = __uint_as_float((unsigned)accB[3]) + __uint_as_float((unsigned)(accB[3] >> 32));
            *(float4*)&pdot[(warp * 2 + 0) * 128 + lane * 4] = ra;
            *(float4*)&pdot[(warp * 2 + 1) * 128 + lane * 4] = rb;
        }
        __syncthreads();

        /* ---- phase 2: thread = (batch b2, row il), warps 0-7 ---- */
        if (tid < 256) {
            float d = 0.f;
            #pragma unroll
            for (int ks = 0; ks < 16; ++ks) d += pdot[(ks * 2 + b2) * 128 + il];
            const float v = em * d * invS;

            float psum = v;
            #pragma unroll
            for (int o = 16; o; o >>= 1) psum += __shfl_xor_sync(0xffffffffu, psum, o);

            /* exchange slice + warp partial to all ranks (DSMEM) */
            const int nb = buf ^ 1;
            float* dst   = uarr + (nb * 2 + b2) * U_STRIDE + iglob;
            float* dslot = uarr + (nb * 2 + b2) * U_STRIDE + 512 + rank * 4 + (warp & 3);
            #pragma unroll
            for (int dr = 0; dr < CLUSTER_N; ++dr) {
                *cluster.map_shared_rank(dst, dr) = v;
                if (lane == 0) *cluster.map_shared_rank(dslot, dr) = psum;
            }
        }
        __syncthreads();

        if (tid < CLUSTER_N) {
            if (t & 1) MBARRIER_ARRIVE_CLUSTER(bar1, tid);
            else       MBARRIER_ARRIVE_CLUSTER(bar0, tid);
        }
    }
}

/* ---------------- launch ---------------- */

extern "C" void kernel_launch(void* const* d_in, const int* in_sizes, int n_in,
                              void* d_out, int out_size)
{
    const float* pi = (const float*)d_in[0];
    const float* A  = (const float*)d_in[1];
    const float* E  = (const float*)d_in[2];
    const int*   x  = (const int*)d_in[3];
    const int*   T  = (const int*)d_in[4];
    float* out = (float*)d_out;

    cudaFuncSetAttribute(hmm_main, cudaFuncAttributeMaxDynamicSharedMemorySize, SMEM_TOTAL);

    prep_logpi<<<1, 256>>>(pi);
    prep_colsum<<<16, 256>>>(A);
    prep_pt<<<N_ST, 256>>>(A);
    prep_logE<<<N_ST, 256>>>(E);
    hmm_main<<<(BATCH / 2) * CLUSTER_N, THREADS, SMEM_TOTAL>>>(x, T, out);
}

// round 8
// speedup vs baseline: 1.2277x; 1.2277x over previous
#include <cuda_runtime.h>
#include <cuda_bf16.h>
#include <cooperative_groups.h>

namespace cg = cooperative_groups;

#define N_ST   512
#define N_OBSV 1024
#define BATCH  64
#define TMAXL  512
#define CLUSTER_N 4
#define THREADS 256

/* ---- device scratch (no allocs) ----
   g_Pp packed-pair P, per (rank, ks, lane) thread block of 128 u32:
   idx = ((rank*8 + ks)*32 + lane)*128 + j*4 + r
   = pack(P[row][k], P[row][k+1]), row = rank*128 + lane*4 + r,
   k = ks*64 + 2*j  (j = 0..31)                                            */
__device__ unsigned g_Pp[512 * 256];
__device__ float g_logET[N_OBSV * N_ST]; /* [obs][state] log emission  */
__device__ float g_expET[N_OBSV * N_ST]; /* [obs][state] emission prob */
__device__ float g_logPi[N_ST];
__device__ float g_icolsum[N_ST];

/* ---------------- PTX helpers ---------------- */

__device__ __forceinline__ unsigned s2u(const void* p) {
    return (unsigned)__cvta_generic_to_shared(p);
}

#define FMA2(acc, a, w) \
    asm("fma.rn.f32x2 %0, %1, %2, %0;" : "+l"(acc) : "l"(a), "l"(w))

#define MBARRIER_INIT(mbar, count) \
    asm volatile("mbarrier.init.shared.b64 [%0], %1;" \
        :: "r"(mbar), "r"((unsigned)(count)) : "memory")

#define MBARRIER_ARRIVE_CLUSTER(local_mbar, target_rank) \
    asm volatile( \
        "{\n\t" \
        ".reg .b32 remAddr32;\n\t" \
        "mapa.shared::cluster.u32 remAddr32, %0, %1;\n\t" \
        "mbarrier.arrive.release.cluster.shared::cluster.b64 _, [remAddr32];\n\t" \
        "}" \
        :: "r"(local_mbar), "r"((unsigned)(target_rank)) : "memory")

#define MBARRIER_WAIT_PARITY(mbar, parity) do { \
    unsigned _m = (mbar), _p = (parity), _done; \
    asm volatile( \
        "{\n\t.reg .pred p;\n\t" \
        "mbarrier.try_wait.parity.acquire.cta.shared::cta.b64 p, [%1], %2;\n\t" \
        "selp.b32 %0, 1, 0, p;\n\t}" \
        : "=r"(_done) : "r"(_m), "r"(_p) : "memory"); \
    if (!_done) { \
        asm volatile( \
            "{\n\t.reg .pred P1;\n\t" \
            "WL_%=:\n\t" \
            "mbarrier.try_wait.parity.acquire.cta.shared::cta.b64 P1, [%0], %1, 0x989680;\n\t" \
            "@P1 bra.uni WD_%=;\n\t" \
            "bra.uni WL_%=;\n\t" \
            "WD_%=:\n\t}" \
            :: "r"(_m), "r"(_p) : "memory"); \
    } \
} while (0)

/* ---------------- prep kernels ---------------- */

__global__ void prep_logpi(const float* __restrict__ pi) {
    __shared__ float red[8];
    int tid = threadIdx.x;
    float s = 0.f;
    for (int k = tid; k < N_ST; k += 256) s += __expf(pi[k]);
    for (int o = 16; o; o >>= 1) s += __shfl_xor_sync(0xffffffffu, s, o);
    if ((tid & 31) == 0) red[tid >> 5] = s;
    __syncthreads();
    float tot = 0.f;
    #pragma unroll
    for (int w = 0; w < 8; w++) tot += red[w];
    float l = __logf(tot);
    for (int k = tid; k < N_ST; k += 256) g_logPi[k] = pi[k] - l;
}

__global__ void prep_colsum(const float* __restrict__ A) {
    __shared__ float part[8][32];
    int kx = threadIdx.x & 31, iy = threadIdx.x >> 5;
    int k = blockIdx.x * 32 + kx;
    float s = 0.f;
    for (int i = iy; i < N_ST; i += 8) s += __expf(A[i * N_ST + k]);
    part[iy][kx] = s;
    __syncthreads();
    if (iy == 0) {
        float t = 0.f;
        #pragma unroll
        for (int j = 0; j < 8; j++) t += part[j][kx];
        g_icolsum[k] = 1.0f / t;
    }
}

/* low16 = bf16(pe) (recovered exactly via <<16); high16 rounded at prep so the
   raw u32 reinterpreted as f32 is the nearest repr of po given fixed low bits */
__device__ __forceinline__ unsigned pack_pair(float pe, float po) {
    unsigned lo = (unsigned)__bfloat16_as_ushort(__float2bfloat16(pe));
    unsigned ob = __float_as_uint(po);
    unsigned hi = (ob - lo + 0x8000u) >> 16;
    return lo | (hi << 16);
}

__global__ void prep_pt(const float* __restrict__ A) {
    int i   = blockIdx.x;        /* global row  */
    int kpg = threadIdx.x;       /* global k-pair 0..255 */
    float p0 = __expf(A[i * N_ST + 2 * kpg])     * g_icolsum[2 * kpg];
    float p1 = __expf(A[i * N_ST + 2 * kpg + 1]) * g_icolsum[2 * kpg + 1];
    int rank = i >> 7, il = i & 127, lane = il >> 2, r = il & 3;
    int ks = kpg >> 5, j = kpg & 31;
    g_Pp[((rank * 8 + ks) * 32 + lane) * 128 + j * 4 + r] = pack_pair(p0, p1);
}

__global__ void prep_logE(const float* __restrict__ E) {
    __shared__ float red[8];
    int i = blockIdx.x;
    int tid = threadIdx.x;
    float s = 0.f;
    for (int o = tid; o < N_OBSV; o += 256) s += __expf(E[i * N_OBSV + o]);
    for (int o = 16; o; o >>= 1) s += __shfl_xor_sync(0xffffffffu, s, o);
    if ((tid & 31) == 0) red[tid >> 5] = s;
    __syncthreads();
    float tot = 0.f;
    #pragma unroll
    for (int w = 0; w < 8; w++) tot += red[w];
    float l = __logf(tot);
    for (int o = tid; o < N_OBSV; o += 256) {
        float lv = E[i * N_OBSV + o] - l;
        g_logET[o * N_ST + i] = lv;
        g_expET[o * N_ST + i] = __expf(lv);
    }
}

/* ---------------- main persistent clustered kernel ---------------- */

#define U_STRIDE 544                               /* 512 u + 16 partials + pad */
#define U_OFF    0
#define PD_OFF   (U_OFF + 2 * 2 * U_STRIDE * 4)    /* 8704  */
#define XS_OFF   (PD_OFF + 8 * 2 * 128 * 4)        /* 16896 */
#define BAR_OFF  (XS_OFF + 2 * TMAXL * 4)          /* 20992 */
#define RED_OFF  (BAR_OFF + 16)
#define SMEM_TOTAL (RED_OFF + 64)

extern __shared__ unsigned char smem_raw[];

__global__ void __cluster_dims__(CLUSTER_N, 1, 1) __launch_bounds__(THREADS, 1)
hmm_main(const int* __restrict__ x, const int* __restrict__ Tarr,
         float* __restrict__ out)
{
    cg::cluster_group cluster = cg::this_cluster();
    const unsigned rank = cluster.block_rank();
    const unsigned grp  = blockIdx.x / CLUSTER_N;

    float* uarr = (float*)(smem_raw + U_OFF);      /* [(buf*2+b)*U_STRIDE+.] */
    float* pdot = (float*)(smem_raw + PD_OFF);     /* [(ks*2+b)*128 + il]    */
    int*   xs   = (int*)(smem_raw + XS_OFF);       /* [b][512]               */
    float* red  = (float*)(smem_raw + RED_OFF);
    const unsigned bar0 = s2u(smem_raw + BAR_OFF);
    const unsigned bar1 = bar0 + 8;

    const int tid  = threadIdx.x;
    const int lane = tid & 31;
    const int warp = tid >> 5;       /* = ks (64-k slice) in dot phase */
    const int b2   = tid >> 7;       /* batch id in scalar phases */
    const int il   = tid & 127;
    const int iglob = rank * 128 + il;

    if (tid == 0) { MBARRIER_INIT(bar0, CLUSTER_N); MBARRIER_INIT(bar1, CLUSTER_N); }

    /* ---- full per-thread P slice into registers (128 packed u32) ---- */
    unsigned Preg[128];
    {
        const uint4* Pg = (const uint4*)g_Pp + ((rank * 8 + warp) * 32 + lane) * 32;
        #pragma unroll
        for (int q = 0; q < 32; ++q) {
            uint4 v = Pg[q];
            Preg[q * 4 + 0] = v.x; Preg[q * 4 + 1] = v.y;
            Preg[q * 4 + 2] = v.z; Preg[q * 4 + 3] = v.w;
        }
    }

    /* preload observation sequences into smem */
    for (int s = tid; s < 2 * TMAXL; s += THREADS)
        xs[s] = x[grp * 2 * TMAXL + s];

    const int T0v = Tarr[grp * 2 + 0];
    const int T1v = Tarr[grp * 2 + 1];
    const int Tc  = max(T0v, T1v);

    /* ---- init: u_0 = exp(alpha0 - m), full & replicated per CTA ---- */
    float C0, C1;
    {
        __syncthreads();   /* xs visible */
        int x0 = xs[b2 * TMAXL];
        float a0i[4];
        float lm = -3.402823466e38f;
        #pragma unroll
        for (int j = 0; j < 4; j++) {
            int s = il + 128 * j;
            a0i[j] = g_logPi[s] + g_logET[x0 * N_ST + s];
            lm = fmaxf(lm, a0i[j]);
        }
        #pragma unroll
        for (int o = 16; o; o >>= 1) lm = fmaxf(lm, __shfl_xor_sync(0xffffffffu, lm, o));
        if (lane == 0) red[warp] = lm;
        __syncthreads();
        const float m0 = fmaxf(fmaxf(red[0], red[1]), fmaxf(red[2], red[3]));
        const float m1 = fmaxf(fmaxf(red[4], red[5]), fmaxf(red[6], red[7]));
        C0 = m0; C1 = m1;
        const float m = b2 ? m1 : m0;
        float* u0b = uarr + b2 * U_STRIDE;
        float ls = 0.f;
        #pragma unroll
        for (int j = 0; j < 4; j++) {
            int s = il + 128 * j;
            float uv = __expf(a0i[j] - m);
            u0b[s] = uv;
            ls += uv;
        }
        #pragma unroll
        for (int o = 16; o; o >>= 1) ls += __shfl_xor_sync(0xffffffffu, ls, o);
        if (lane == 0) u0b[512 + (warp & 3)] = ls;
        if (il >= 4 && il < 16) u0b[512 + il] = 0.f;
        __syncthreads();
    }
    cluster.sync();   /* barrier init + u0 ready everywhere */

    unsigned ph0 = 0, ph1 = 0;

    for (int t = 0; t < Tc; ++t) {
        if (t > 0) {
            if ((t - 1) & 1) { MBARRIER_WAIT_PARITY(bar1, ph1); ph1 ^= 1; }
            else             { MBARRIER_WAIT_PARITY(bar0, ph0); ph0 ^= 1; }
        }

        const int buf = t & 1;
        float* ub0 = uarr + (buf * 2 + 0) * U_STRIDE;
        float* ub1 = uarr + (buf * 2 + 1) * U_STRIDE;

        /* prefetch emission for phase 2 (LDG latency hidden by dot) */
        const int   xv = xs[b2 * TMAXL + ((t + 1 < Tc) ? (t + 1) : t)];
        const float em = g_expET[xv * N_ST + iglob];

        /* ---- dot phase: warp = 64-k slice, lane = 4-row group ----
           P entirely in registers; w broadcast from smem; FFMA2      */
        {
            const ulonglong2* U0 = (const ulonglong2*)(ub0 + warp * 64);
            const ulonglong2* U1 = (const ulonglong2*)(ub1 + warp * 64);
            unsigned long long accA[4] = {0ull, 0ull, 0ull, 0ull};
            unsigned long long accB[4] = {0ull, 0ull, 0ull, 0ull};

            #pragma unroll
            for (int jj = 0; jj < 16; ++jj) {
                ulonglong2 W0 = U0[jj];
                ulonglong2 W1 = U1[jj];
                #pragma unroll
                for (int sub = 0; sub < 2; ++sub) {
                    unsigned long long w0 = sub ? W0.y : W0.x;
                    unsigned long long w1 = sub ? W1.y : W1.x;
                    #pragma unroll
                    for (int r = 0; r < 4; ++r) {
                        unsigned q = Preg[(2 * jj + sub) * 4 + r];
                        unsigned long long a =
                            ((unsigned long long)q << 32) | (unsigned)(q << 16);
                        FMA2(accA[r], a, w0);
                        FMA2(accB[r], a, w1);
                    }
                }
            }

            float4 ra, rb;
            ra.x = __uint_as_float((unsigned)accA[0]) + __uint_as_float((unsigned)(accA[0] >> 32));
            ra.y = __uint_as_float((unsigned)accA[1]) + __uint_as_float((unsigned)(accA[1] >> 32));
            ra.z = __uint_as_float((unsigned)accA[2]) + __uint_as_float((unsigned)(accA[2] >> 32));
            ra.w = __uint_as_float((unsigned)accA[3]) + __uint_as_float((unsigned)(accA[3] >> 32));
            rb.x = __uint_as_float((unsigned)accB[0]) + __uint_as_float((unsigned)(accB[0] >> 32));
            rb.y = __uint_as_float((unsigned)accB[1]) + __uint_as_float((unsigned)(accB[1] >> 32));
            rb.z = __uint_as_float((unsigned)accB[2]) + __uint_as_float((unsigned)(accB[2] >> 32));
            rb.w = __uint_as_float((unsigned)accB[3]) + __uint_as_float((unsigned)(accB[3] >> 32));
            *(float4*)&pdot[(warp * 2 + 0) * 128 + lane * 4] = ra;
            *(float4*)&pdot[(warp * 2 + 1) * 128 + lane * 4] = rb;
        }

        /* ---- S block (off the post-wait critical path) ---- */
        float4 p0a = *(const float4*)(ub0 + 512), p0b = *(const float4*)(ub0 + 516);
        float4 p0c = *(const float4*)(ub0 + 520), p0d = *(const float4*)(ub0 + 524);
        float4 p1a = *(const float4*)(ub1 + 512), p1b = *(const float4*)(ub1 + 516);
        float4 p1c = *(const float4*)(ub1 + 520), p1d = *(const float4*)(ub1 + 524);
        const float S0 = (((p0a.x + p0a.y) + (p0a.z + p0a.w)) + ((p0b.x + p0b.y) + (p0b.z + p0b.w)))
                       + (((p0c.x + p0c.y) + (p0c.z + p0c.w)) + ((p0d.x + p0d.y) + (p0d.z + p0d.w)));
        const float S1 = (((p1a.x + p1a.y) + (p1a.z + p1a.w)) + ((p1b.x + p1b.y) + (p1b.z + p1b.w)))
                       + (((p1c.x + p1c.y) + (p1c.z + p1c.w)) + ((p1d.x + p1d.y) + (p1d.z + p1d.w)));
        C0 += __logf(S0);
        C1 += __logf(S1);

        if (rank == 0 && tid == 0) {
            if (t == T0v - 1) out[grp * 2 + 0] = C0;
            if (t == T1v - 1) out[grp * 2 + 1] = C1;
        }
        if (t == Tc - 1) break;

        const float invS = __frcp_rn(b2 ? S1 : S0);
        __syncthreads();

        /* ---- phase 2: thread = (batch b2, row il) ---- */
        float d = 0.f;
        #pragma unroll
        for (int ks = 0; ks < 8; ++ks) d += pdot[(ks * 2 + b2) * 128 + il];
        const float v = em * d * invS;

        float psum = v;
        #pragma unroll
        for (int o = 16; o; o >>= 1) psum += __shfl_xor_sync(0xffffffffu, psum, o);

        /* exchange slice + warp partial to all ranks (DSMEM) */
        const int nb = buf ^ 1;
        float* dst   = uarr + (nb * 2 + b2) * U_STRIDE + iglob;
        float* dslot = uarr + (nb * 2 + b2) * U_STRIDE + 512 + rank * 4 + (warp & 3);
        #pragma unroll
        for (int dr = 0; dr < CLUSTER_N; ++dr) {
            *cluster.map_shared_rank(dst, dr) = v;
            if (lane == 0) *cluster.map_shared_rank(dslot, dr) = psum;
        }
        __syncthreads();

        if (tid < CLUSTER_N) {
            if (t & 1) MBARRIER_ARRIVE_CLUSTER(bar1, tid);
            else       MBARRIER_ARRIVE_CLUSTER(bar0, tid);
        }
    }
}

/* ---------------- launch ---------------- */

extern "C" void kernel_launch(void* const* d_in, const int* in_sizes, int n_in,
                              void* d_out, int out_size)
{
    const float* pi = (const float*)d_in[0];
    const float* A  = (const float*)d_in[1];
    const float* E  = (const float*)d_in[2];
    const int*   x  = (const int*)d_in[3];
    const int*   T  = (const int*)d_in[4];
    float* out = (float*)d_out;

    cudaFuncSetAttribute(hmm_main, cudaFuncAttributeMaxDynamicSharedMemorySize, SMEM_TOTAL);

    prep_logpi<<<1, 256>>>(pi);
    prep_colsum<<<16, 256>>>(A);
    prep_pt<<<N_ST, 256>>>(A);
    prep_logE<<<N_ST, 256>>>(E);
    hmm_main<<<(BATCH / 2) * CLUSTER_N, THREADS, SMEM_TOTAL>>>(x, T, out);
}

// round 11
// speedup vs baseline: 1.4872x; 1.2114x over previous
#include <cuda_runtime.h>
#include <cuda_bf16.h>
#include <cooperative_groups.h>

namespace cg = cooperative_groups;

#define N_ST   512
#define N_OBSV 1024
#define BATCH  64
#define TMAXL  512
#define CLUSTER_N 4
#define THREADS 512

/* ---- device scratch (no allocs) ----
   g_P4[kp*128 + rank*32 + rg] : uint4 = rows (4rg..4rg+3) of CTA 'rank',
   each u32 = compensation-packed pair (P[r][2kp], P[r][2kp+1])            */
__device__ uint4 g_P4[256 * 128];
__device__ float g_logET[N_OBSV * N_ST]; /* [obs][state] log emission  */
__device__ float g_expET[N_OBSV * N_ST]; /* [obs][state] emission prob */
__device__ float g_logPi[N_ST];
__device__ float g_icolsum[N_ST];

/* ---------------- PTX helpers ---------------- */

__device__ __forceinline__ unsigned s2u(const void* p) {
    return (unsigned)__cvta_generic_to_shared(p);
}

#define FMA2(acc, a, w) \
    asm("fma.rn.f32x2 %0, %1, %2, %0;" : "+l"(acc) : "l"(a), "l"(w))

#define MBARRIER_INIT(mbar, count) \
    asm volatile("mbarrier.init.shared.b64 [%0], %1;" \
        :: "r"(mbar), "r"((unsigned)(count)) : "memory")

#define MBARRIER_ARRIVE_CLUSTER(local_mbar, target_rank) \
    asm volatile( \
        "{\n\t" \
        ".reg .b32 remAddr32;\n\t" \
        "mapa.shared::cluster.u32 remAddr32, %0, %1;\n\t" \
        "mbarrier.arrive.release.cluster.shared::cluster.b64 _, [remAddr32];\n\t" \
        "}" \
        :: "r"(local_mbar), "r"((unsigned)(target_rank)) : "memory")

#define MBARRIER_WAIT_PARITY(mbar, parity) do { \
    unsigned _m = (mbar), _p = (parity), _done; \
    asm volatile( \
        "{\n\t.reg .pred p;\n\t" \
        "mbarrier.try_wait.parity.acquire.cta.shared::cta.b64 p, [%1], %2;\n\t" \
        "selp.b32 %0, 1, 0, p;\n\t}" \
        : "=r"(_done) : "r"(_m), "r"(_p) : "memory"); \
    if (!_done) { \
        asm volatile( \
            "{\n\t.reg .pred P1;\n\t" \
            "WL_%=:\n\t" \
            "mbarrier.try_wait.parity.acquire.cta.shared::cta.b64 P1, [%0], %1, 0x989680;\n\t" \
            "@P1 bra.uni WD_%=;\n\t" \
            "bra.uni WL_%=;\n\t" \
            "WD_%=:\n\t}" \
            :: "r"(_m), "r"(_p) : "memory"); \
    } \
} while (0)

/* ---------------- prep kernels ---------------- */

__global__ void prep_logpi(const float* __restrict__ pi) {
    __shared__ float red[8];
    int tid = threadIdx.x;
    float s = 0.f;
    for (int k = tid; k < N_ST; k += 256) s += __expf(pi[k]);
    for (int o = 16; o; o >>= 1) s += __shfl_xor_sync(0xffffffffu, s, o);
    if ((tid & 31) == 0) red[tid >> 5] = s;
    __syncthreads();
    float tot = 0.f;
    #pragma unroll
    for (int w = 0; w < 8; w++) tot += red[w];
    float l = __logf(tot);
    for (int k = tid; k < N_ST; k += 256) g_logPi[k] = pi[k] - l;
}

__global__ void prep_colsum(const float* __restrict__ A) {
    __shared__ float part[8][32];
    int kx = threadIdx.x & 31, iy = threadIdx.x >> 5;
    int k = blockIdx.x * 32 + kx;
    float s = 0.f;
    for (int i = iy; i < N_ST; i += 8) s += __expf(A[i * N_ST + k]);
    part[iy][kx] = s;
    __syncthreads();
    if (iy == 0) {
        float t = 0.f;
        #pragma unroll
        for (int j = 0; j < 8; j++) t += part[j][kx];
        g_icolsum[k] = 1.0f / t;
    }
}

/* low16 = bf16(pe) (recovered exactly via <<16); high16 rounded at prep so the
   raw u32 reinterpreted as f32 is the nearest repr of po given fixed low bits */
__device__ __forceinline__ unsigned pack_pair(float pe, float po) {
    unsigned lo = (unsigned)__bfloat16_as_ushort(__float2bfloat16(pe));
    unsigned ob = __float_as_uint(po);
    unsigned hi = (ob - lo + 0x8000u) >> 16;
    return lo | (hi << 16);
}

__global__ void prep_pt(const float* __restrict__ A) {
    int i  = blockIdx.x;        /* row  */
    int kp = threadIdx.x;       /* 0..255 k-pair */
    float p0 = __expf(A[i * N_ST + 2 * kp])     * g_icolsum[2 * kp];
    float p1 = __expf(A[i * N_ST + 2 * kp + 1]) * g_icolsum[2 * kp + 1];
    int rank = i >> 7, rg = (i >> 2) & 31, j = i & 3;
    ((unsigned*)g_P4)[((kp * 128) + rank * 32 + rg) * 4 + j] = pack_pair(p0, p1);
}

__global__ void prep_logE(const float* __restrict__ E) {
    __shared__ float red[8];
    int i = blockIdx.x;
    int tid = threadIdx.x;
    float s = 0.f;
    for (int o = tid; o < N_OBSV; o += 256) s += __expf(E[i * N_OBSV + o]);
    for (int o = 16; o; o >>= 1) s += __shfl_xor_sync(0xffffffffu, s, o);
    if ((tid & 31) == 0) red[tid >> 5] = s;
    __syncthreads();
    float tot = 0.f;
    #pragma unroll
    for (int w = 0; w < 8; w++) tot += red[w];
    float l = __logf(tot);
    for (int o = tid; o < N_OBSV; o += 256) {
        float lv = E[i * N_OBSV + o] - l;
        g_logET[o * N_ST + i] = lv;
        g_expET[o * N_ST + i] = __expf(lv);
    }
}

/* ---------------- main persistent clustered kernel ---------------- */

#define U_STRIDE 544                               /* 512 u + 16 partials + pad */
#define P_BYTES  131072
#define U_OFF    P_BYTES
#define PD_OFF   (U_OFF + 2 * 2 * U_STRIDE * 4)    /* 148480 */
#define XS_OFF   (PD_OFF + 16 * 2 * 128 * 4)       /* 164864 */
#define BAR_OFF  (XS_OFF + 2 * TMAXL * 4)          /* 168960 */
#define RED_OFF  (BAR_OFF + 16)
#define SMEM_TOTAL (RED_OFF + 64)

extern __shared__ unsigned char smem_raw[];

__global__ void __cluster_dims__(CLUSTER_N, 1, 1) __launch_bounds__(THREADS, 1)
hmm_main(const int* __restrict__ x, const int* __restrict__ Tarr,
         float* __restrict__ out)
{
    cg::cluster_group cluster = cg::this_cluster();
    const unsigned rank = cluster.block_rank();
    const unsigned grp  = blockIdx.x / CLUSTER_N;

    uint4* Ps   = (uint4*)smem_raw;                 /* [kp*32 + rg]            */
    float* uarr = (float*)(smem_raw + U_OFF);       /* [(buf*2+b)*U_STRIDE+.]  */
    float* pdot = (float*)(smem_raw + PD_OFF);      /* [(ks*2+b)*128 + il]     */
    int*   xs   = (int*)(smem_raw + XS_OFF);        /* [b][512]                */
    float* red  = (float*)(smem_raw + RED_OFF);
    const unsigned bar0 = s2u(smem_raw + BAR_OFF);
    const unsigned bar1 = bar0 + 8;

    const int tid  = threadIdx.x;
    const int lane = tid & 31;
    const int warp = tid >> 5;       /* = ks (32-k slice) in dot phase */
    const int b2   = (tid >> 7) & 1; /* batch id in scalar phases (tid<256) */
    const int il   = tid & 127;
    const int iglob = rank * 128 + il;

    if (tid == 0) { MBARRIER_INIT(bar0, CLUSTER_N); MBARRIER_INIT(bar1, CLUSTER_N); }

    /* load P slice (coalesced 16B) */
    for (int s = tid; s < 8192; s += THREADS) {
        int kp = s >> 5, rg = s & 31;
        Ps[s] = g_P4[kp * 128 + rank * 32 + rg];
    }

    /* preload observation sequences into smem */
    for (int s = tid; s < 2 * TMAXL; s += THREADS)
        xs[s] = x[grp * 2 * TMAXL + s];

    const int T0v = Tarr[grp * 2 + 0];
    const int T1v = Tarr[grp * 2 + 1];
    const int Tc  = max(T0v, T1v);

    /* ---- init: u_0 = exp(alpha0 - m), full & replicated per CTA ---- */
    float C0, C1;
    {
        __syncthreads();   /* xs + P visible */
        float a0i[4];
        float lm = -3.402823466e38f;
        if (tid < 256) {
            int x0 = xs[b2 * TMAXL];
            #pragma unroll
            for (int j = 0; j < 4; j++) {
                int s = il + 128 * j;
                a0i[j] = g_logPi[s] + g_logET[x0 * N_ST + s];
                lm = fmaxf(lm, a0i[j]);
            }
            #pragma unroll
            for (int o = 16; o; o >>= 1) lm = fmaxf(lm, __shfl_xor_sync(0xffffffffu, lm, o));
            if (lane == 0) red[warp] = lm;
        }
        __syncthreads();
        const float m0 = fmaxf(fmaxf(red[0], red[1]), fmaxf(red[2], red[3]));
        const float m1 = fmaxf(fmaxf(red[4], red[5]), fmaxf(red[6], red[7]));
        C0 = m0; C1 = m1;
        if (tid < 256) {
            const float m = b2 ? m1 : m0;
            float* u0b = uarr + b2 * U_STRIDE;
            float ls = 0.f;
            #pragma unroll
            for (int j = 0; j < 4; j++) {
                int s = il + 128 * j;
                float uv = __expf(a0i[j] - m);
                u0b[s] = uv;
                ls += uv;
            }
            #pragma unroll
            for (int o = 16; o; o >>= 1) ls += __shfl_xor_sync(0xffffffffu, ls, o);
            if (lane == 0) u0b[512 + (warp & 3)] = ls;
            if (il >= 4 && il < 16) u0b[512 + il] = 0.f;
        }
        __syncthreads();
    }
    cluster.sync();   /* barrier init + u0 ready everywhere */

    unsigned ph0 = 0, ph1 = 0;

    for (int t = 0; t < Tc; ++t) {
        if (t > 0) {
            if ((t - 1) & 1) { MBARRIER_WAIT_PARITY(bar1, ph1); ph1 ^= 1; }
            else             { MBARRIER_WAIT_PARITY(bar0, ph0); ph0 ^= 1; }
        }

        const int buf = t & 1;
        float* ub0 = uarr + (buf * 2 + 0) * U_STRIDE;
        float* ub1 = uarr + (buf * 2 + 1) * U_STRIDE;

        /* emission prefetch for phase 2 (long-latency LDG, hidden by dot) */
        float em = 0.f;
        if (tid < 256) {
            const int xv = xs[b2 * TMAXL + ((t + 1 < Tc) ? (t + 1) : t)];
            em = g_expET[xv * N_ST + iglob];
        }

        /* ---- dot phase: warp = 32-k slice, lane = 4-row group ----
           P packed pairs from smem, w broadcast from smem, FFMA2      */
        {
            const int ks = warp;
            const uint4* Pp = Ps + (ks * 16) * 32 + lane;
            const ulonglong2* U0 = (const ulonglong2*)(ub0 + ks * 32);
            const ulonglong2* U1 = (const ulonglong2*)(ub1 + ks * 32);

            unsigned long long accA0 = 0, accA1 = 0, accA2 = 0, accA3 = 0;
            unsigned long long accB0 = 0, accB1 = 0, accB2 = 0, accB3 = 0;

            #pragma unroll
            for (int kp2 = 0; kp2 < 8; ++kp2) {
                uint4 qa = Pp[(2 * kp2) * 32];
                uint4 qb = Pp[(2 * kp2 + 1) * 32];
                ulonglong2 W0 = U0[kp2];
                ulonglong2 W1 = U1[kp2];

                unsigned long long a0, a1, a2, a3;
                a0 = ((unsigned long long)qa.x << 32) | (unsigned)(qa.x << 16);
                a1 = ((unsigned long long)qa.y << 32) | (unsigned)(qa.y << 16);
                a2 = ((unsigned long long)qa.z << 32) | (unsigned)(qa.z << 16);
                a3 = ((unsigned long long)qa.w << 32) | (unsigned)(qa.w << 16);
                FMA2(accA0, a0, W0.x);  FMA2(accB0, a0, W1.x);
                FMA2(accA1, a1, W0.x);  FMA2(accB1, a1, W1.x);
                FMA2(accA2, a2, W0.x);  FMA2(accB2, a2, W1.x);
                FMA2(accA3, a3, W0.x);  FMA2(accB3, a3, W1.x);

                a0 = ((unsigned long long)qb.x << 32) | (unsigned)(qb.x << 16);
                a1 = ((unsigned long long)qb.y << 32) | (unsigned)(qb.y << 16);
                a2 = ((unsigned long long)qb.z << 32) | (unsigned)(qb.z << 16);
                a3 = ((unsigned long long)qb.w << 32) | (unsigned)(qb.w << 16);
                FMA2(accA0, a0, W0.y);  FMA2(accB0, a0, W1.y);
                FMA2(accA1, a1, W0.y);  FMA2(accB1, a1, W1.y);
                FMA2(accA2, a2, W0.y);  FMA2(accB2, a2, W1.y);
                FMA2(accA3, a3, W0.y);  FMA2(accB3, a3, W1.y);
            }

            float4 ra, rb;
            ra.x = __uint_as_float((unsigned)accA0) + __uint_as_float((unsigned)(accA0 >> 32));
            ra.y = __uint_as_float((unsigned)accA1) + __uint_as_float((unsigned)(accA1 >> 32));
            ra.z = __uint_as_float((unsigned)accA2) + __uint_as_float((unsigned)(accA2 >> 32));
            ra.w = __uint_as_float((unsigned)accA3) + __uint_as_float((unsigned)(accA3 >> 32));
            rb.x = __uint_as_float((unsigned)accB0) + __uint_as_float((unsigned)(accB0 >> 32));
            rb.y = __uint_as_float((unsigned)accB1) + __uint_as_float((unsigned)(accB1 >> 32));
            rb.z = __uint_as_float((unsigned)accB2) + __uint_as_float((unsigned)(accB2 >> 32));
            rb.w = __uint_as_float((unsigned)accB3) + __uint_as_float((unsigned)(accB3 >> 32));
            *(float4*)&pdot[(ks * 2 + 0) * 128 + lane * 4] = ra;
            *(float4*)&pdot[(ks * 2 + 1) * 128 + lane * 4] = rb;
        }

        /* ---- S block (off the post-wait critical path) ---- */
        float4 p0a = *(const float4*)(ub0 + 512), p0b = *(const float4*)(ub0 + 516);
        float4 p0c = *(const float4*)(ub0 + 520), p0d = *(const float4*)(ub0 + 524);
        float4 p1a = *(const float4*)(ub1 + 512), p1b = *(const float4*)(ub1 + 516);
        float4 p1c = *(const float4*)(ub1 + 520), p1d = *(const float4*)(ub1 + 524);
        const float S0 = (((p0a.x + p0a.y) + (p0a.z + p0a.w)) + ((p0b.x + p0b.y) + (p0b.z + p0b.w)))
                       + (((p0c.x + p0c.y) + (p0c.z + p0c.w)) + ((p0d.x + p0d.y) + (p0d.z + p0d.w)));
        const float S1 = (((p1a.x + p1a.y) + (p1a.z + p1a.w)) + ((p1b.x + p1b.y) + (p1b.z + p1b.w)))
                       + (((p1c.x + p1c.y) + (p1c.z + p1c.w)) + ((p1d.x + p1d.y) + (p1d.z + p1d.w)));
        C0 += __logf(S0);
        C1 += __logf(S1);

        if (rank == 0 && tid == 0) {
            if (t == T0v - 1) out[grp * 2 + 0] = C0;
            if (t == T1v - 1) out[grp * 2 + 1] = C1;
        }
        if (t == Tc - 1) break;

        const float invS = __frcp_rn(b2 ? S1 : S0);
        __syncthreads();

        /* ---- phase 2: thread = (batch b2, row il), tid < 256 ---- */
        if (tid < 256) {
            float d = 0.f;
            #pragma unroll
            for (int ks = 0; ks < 16; ++ks) d += pdot[(ks * 2 + b2) * 128 + il];
            const float v = em * d * invS;

            float psum = v;
            #pragma unroll
            for (int o = 16; o; o >>= 1) psum += __shfl_xor_sync(0xffffffffu, psum, o);

            /* exchange slice + warp partial to all ranks (DSMEM) */
            const int nb = buf ^ 1;
            float* dst   = uarr + (nb * 2 + b2) * U_STRIDE + iglob;
            float* dslot = uarr + (nb * 2 + b2) * U_STRIDE + 512 + rank * 4 + (warp & 3);
            #pragma unroll
            for (int dr = 0; dr < CLUSTER_N; ++dr) {
                *cluster.map_shared_rank(dst, dr) = v;
                if (lane == 0) *cluster.map_shared_rank(dslot, dr) = psum;
            }
        }
        __syncthreads();

        if (tid < CLUSTER_N) {
            if (t & 1) MBARRIER_ARRIVE_CLUSTER(bar1, tid);
            else       MBARRIER_ARRIVE_CLUSTER(bar0, tid);
        }
    }
}

/* ---------------- launch ---------------- */

extern "C" void kernel_launch(void* const* d_in, const int* in_sizes, int n_in,
                              void* d_out, int out_size)
{
    const float* pi = (const float*)d_in[0];
    const float* A  = (const float*)d_in[1];
    const float* E  = (const float*)d_in[2];
    const int*   x  = (const int*)d_in[3];
    const int*   T  = (const int*)d_in[4];
    float* out = (float*)d_out;

    cudaFuncSetAttribute(hmm_main, cudaFuncAttributeMaxDynamicSharedMemorySize, SMEM_TOTAL);

    prep_logpi<<<1, 256>>>(pi);
    prep_colsum<<<16, 256>>>(A);
    prep_pt<<<N_ST, 256>>>(A);
    prep_logE<<<N_ST, 256>>>(E);
    hmm_main<<<(BATCH / 2) * CLUSTER_N, THREADS, SMEM_TOTAL>>>(x, T, out);
}